// round 8
// baseline (speedup 1.0000x reference)
#include <cuda_runtime.h>
#include <cuda_bf16.h>
#include <math.h>
#include <stdint.h>

// GLIF recurrence, T=4. One block per channel (grid=2048, 256 threads),
// 16 batches/block. Prefetch via cp.async into a 4-stage SMEM ring
// (16B/thread/stage) -> registers freed, occupancy up, deep MLP.
// Each thread consumes only its own smem slot => NO barriers in the loop.
// Compute in packed f32x2 (bit-identical ordering to the scalar reference path).
//
// x: (B=16, PLANE=2048, L=1024) fp32. out: final spike map, fp32 {0,1}.

#define GLIF_T     4
#define GLIF_PLANE 2048
#define GLIF_L     1024
#define GLIF_B     16
#define STAGES     4

// ---- packed f32x2 helpers ----
__device__ __forceinline__ uint64_t pk2(float lo, float hi) {
    uint64_t r;
    asm("mov.b64 %0, {%1, %2};" : "=l"(r) : "f"(lo), "f"(hi));
    return r;
}
__device__ __forceinline__ void upk2(uint64_t v, float& lo, float& hi) {
    asm("mov.b64 {%0, %1}, %2;" : "=f"(lo), "=f"(hi) : "l"(v));
}
__device__ __forceinline__ uint64_t fma2_(uint64_t a, uint64_t b, uint64_t c) {
    uint64_t d;
    asm("fma.rn.f32x2 %0, %1, %2, %3;" : "=l"(d) : "l"(a), "l"(b), "l"(c));
    return d;
}
__device__ __forceinline__ uint64_t mul2_(uint64_t a, uint64_t b) {
    uint64_t d;
    asm("mul.rn.f32x2 %0, %1, %2;" : "=l"(d) : "l"(a), "l"(b));
    return d;
}
__device__ __forceinline__ uint64_t add2_(uint64_t a, uint64_t b) {
    uint64_t d;
    asm("add.rn.f32x2 %0, %1, %2;" : "=l"(d) : "l"(a), "l"(b));
    return d;
}
__device__ __forceinline__ float setgt_(float a, float b) {
    float r;
    asm("set.gt.f32.f32 %0, %1, %2;" : "=f"(r) : "f"(a), "f"(b));
    return r;  // 1.0f if a > b else 0.0f
}

__device__ __forceinline__ uint32_t smem_u32(const void* p) {
    uint32_t a;
    asm("{ .reg .u64 t; cvta.to.shared.u64 t, %1; cvt.u32.u64 %0, t; }"
        : "=r"(a) : "l"(p));
    return a;
}
__device__ __forceinline__ void cp_async16(uint32_t smem_addr, const void* gmem) {
    asm volatile("cp.async.cg.shared.global [%0], [%1], 16;"
                 :: "r"(smem_addr), "l"(gmem));
}
__device__ __forceinline__ void cp_commit() {
    asm volatile("cp.async.commit_group;");
}
__device__ __forceinline__ void cp_wait3() {
    asm volatile("cp.async.wait_group 3;");
}

__global__ void __launch_bounds__(256, 6) glif_kernel(
    const float* __restrict__ x,
    const float* __restrict__ alpha,
    const float* __restrict__ beta,
    const float* __restrict__ gamma,
    const float* __restrict__ tau,
    const float* __restrict__ Vth,
    const float* __restrict__ leak,
    const float* __restrict__ reVth,
    const float* __restrict__ conduct,
    float* __restrict__ out)
{
    __shared__ float sp[10];
    __shared__ float4 buf[STAGES][256];

    const int c   = blockIdx.x;            // channel
    const int tid = threadIdx.x;

    const size_t row4  = (size_t)GLIF_PLANE * (GLIF_L / 4);  // float4 per batch
    const size_t base4 = (size_t)c * (GLIF_L / 4) + tid;
    const float4* xp = reinterpret_cast<const float4*>(x) + base4;
    float4*       op = reinterpret_cast<float4*>(out) + base4;

    const uint32_t mybuf = smem_u32(&buf[0][tid]);   // stage stride = 4096B

    // ---- prologue: issue first STAGES-1 batches ----
#pragma unroll
    for (int i = 0; i < STAGES - 1; ++i) {
        cp_async16(mybuf + (uint32_t)i * 4096u, xp + (size_t)i * row4);
        cp_commit();
    }

    // ---- per-channel params: warp 0, lanes 0-7 each own one sigmoid ----
    if (tid < 32) {
        const int lane = tid;
        const float al = (__ldg(&alpha[c]) > 0.0f) ? 1.0f : 0.0f;  // arch_act(sigmoid)==(p>0)
        const float be = (__ldg(&beta[c])  > 0.0f) ? 1.0f : 0.0f;
        const float ga = (__ldg(&gamma[c]) > 0.0f) ? 1.0f : 0.0f;

        float v = 0.0f;
        if      (lane == 0) v = tau[c];
        else if (lane == 1) v = Vth[c];
        else if (lane == 2) v = leak[c];
        else if (lane == 3) v = reVth[c];
        else if (lane >= 4 && lane < 8) v = conduct[(lane - 4) * GLIF_PLANE + c];

        const float sig = 1.0f / (1.0f + expf(-v));

        if (lane == 0) {
            sp[0] = 1.0f - al * (1.0f - sig);   // A
            sp[1] = -ga;                        // negGa (g = 1 - ga*o)
        } else if (lane == 1) {
            sp[4] = sig;                        // vth
        } else if (lane == 2) {
            sp[2] = -((1.0f - al) * sig);       // negLk
        } else if (lane == 3) {
            sp[3] = -((1.0f - ga) * sig);       // negR
        } else if (lane >= 4 && lane < 8) {
            sp[5 + (lane - 4)] = 1.0f - be * (1.0f - sig);  // s_t
        }
    }
    __syncthreads();

    const uint64_t A2     = pk2(sp[0], sp[0]);
    const uint64_t negGa2 = pk2(sp[1], sp[1]);
    const uint64_t negLk2 = pk2(sp[2], sp[2]);
    const uint64_t negR2  = pk2(sp[3], sp[3]);
    const float    vth    = sp[4];
    const uint64_t s02    = pk2(sp[5], sp[5]);
    uint64_t sT2[3];
    sT2[0] = pk2(sp[6], sp[6]);
    sT2[1] = pk2(sp[7], sp[7]);
    sT2[2] = pk2(sp[8], sp[8]);
    const uint64_t one2   = pk2(1.0f, 1.0f);

    // ---- main loop: 16 batches through the 4-stage ring ----
#pragma unroll 4
    for (int i = 0; i < GLIF_B; ++i) {
        // producer: batch i+STAGES-1 (always one commit per iteration so the
        // wait-group accounting stays exact in the tail)
        if (i + STAGES - 1 < GLIF_B) {
            cp_async16(mybuf + (uint32_t)((i + STAGES - 1) & (STAGES - 1)) * 4096u,
                       xp + (size_t)(i + STAGES - 1) * row4);
        }
        cp_commit();
        cp_wait3();   // <=3 newer groups pending => batch i complete

        const float4 xq = buf[i & (STAGES - 1)][tid];
        float oo[4];

#pragma unroll
        for (int p = 0; p < 2; ++p) {
            const uint64_t x2 = (p == 0) ? pk2(xq.x, xq.y) : pk2(xq.z, xq.w);

            // t = 0: u=0, o=0 -> u1 = x*s0 - Lk
            uint64_t m = fma2_(x2, s02, negLk2);
            float mlo, mhi;
            upk2(m, mlo, mhi);
            float olo = setgt_(mlo, vth);
            float ohi = setgt_(mhi, vth);

#pragma unroll
            for (int t = 0; t < 3; ++t) {
                const uint64_t o2 = pk2(olo, ohi);
                // reference order: ((A*u)*(1-ga*o) - Lk) + x*s - R*o
                const uint64_t g = fma2_(negGa2, o2, one2);  // exact: o,ga in {0,1}
                uint64_t a = mul2_(A2, m);
                a = mul2_(a, g);
                a = add2_(a, negLk2);
                a = fma2_(x2, sT2[t], a);
                m = fma2_(negR2, o2, a);                      // exact: o in {0,1}
                upk2(m, mlo, mhi);
                olo = setgt_(mlo, vth);
                ohi = setgt_(mhi, vth);
            }
            oo[2 * p]     = olo;
            oo[2 * p + 1] = ohi;
        }

        float4 res;
        res.x = oo[0]; res.y = oo[1]; res.z = oo[2]; res.w = oo[3];
        __stcs(op + (size_t)i * row4, res);
    }
}

extern "C" void kernel_launch(void* const* d_in, const int* in_sizes, int n_in,
                              void* d_out, int out_size) {
    const float* x       = (const float*)d_in[0];
    const float* alpha   = (const float*)d_in[1];
    const float* beta    = (const float*)d_in[2];
    const float* gamma   = (const float*)d_in[3];
    const float* tau     = (const float*)d_in[4];
    const float* Vth     = (const float*)d_in[5];
    const float* leak    = (const float*)d_in[6];
    const float* reVth   = (const float*)d_in[7];
    const float* conduct = (const float*)d_in[8];
    float* out = (float*)d_out;

    glif_kernel<<<GLIF_PLANE, 256>>>(x, alpha, beta, gamma, tau, Vth,
                                     leak, reVth, conduct, out);
}

// round 9
// speedup vs baseline: 1.0853x; 1.0853x over previous
#include <cuda_runtime.h>
#include <cuda_bf16.h>
#include <math.h>
#include <stdint.h>

// GLIF recurrence, T=4. Contiguous-row decomposition:
// grid = 2048 blocks x 256 threads; block b owns 16 consecutive rows
// (64 KiB contiguous). Iteration i processes row i (4 KiB, block-wide
// coalesced, address = base + i*4096 -> immediate-offset LDG/STG).
// The 16 rows are 16 consecutive channels; params for all 16 computed
// warp-parallel (128 lanes, one sigmoid each) into a float2 smem table,
// consumed per-iteration as broadcast LDS.64 packed constants.
// Recurrence in packed f32x2, ordering bit-identical to the reference.
//
// x: (B=16, PLANE=2048, L=1024) fp32. out: final spike map, fp32 {0,1}.

#define GLIF_T      4
#define GLIF_PLANE  2048
#define GLIF_L      1024
#define ROWS_PER_BLK 16

// ---- packed f32x2 helpers ----
__device__ __forceinline__ uint64_t pk2(float lo, float hi) {
    uint64_t r;
    asm("mov.b64 %0, {%1, %2};" : "=l"(r) : "f"(lo), "f"(hi));
    return r;
}
__device__ __forceinline__ void upk2(uint64_t v, float& lo, float& hi) {
    asm("mov.b64 {%0, %1}, %2;" : "=f"(lo), "=f"(hi) : "l"(v));
}
__device__ __forceinline__ uint64_t fma2_(uint64_t a, uint64_t b, uint64_t c) {
    uint64_t d;
    asm("fma.rn.f32x2 %0, %1, %2, %3;" : "=l"(d) : "l"(a), "l"(b), "l"(c));
    return d;
}
__device__ __forceinline__ uint64_t mul2_(uint64_t a, uint64_t b) {
    uint64_t d;
    asm("mul.rn.f32x2 %0, %1, %2;" : "=l"(d) : "l"(a), "l"(b));
    return d;
}
__device__ __forceinline__ uint64_t add2_(uint64_t a, uint64_t b) {
    uint64_t d;
    asm("add.rn.f32x2 %0, %1, %2;" : "=l"(d) : "l"(a), "l"(b));
    return d;
}
__device__ __forceinline__ float setgt_(float a, float b) {
    float r;
    asm("set.gt.f32.f32 %0, %1, %2;" : "=f"(r) : "f"(a), "f"(b));
    return r;  // 1.0f if a > b else 0.0f
}

__global__ void __launch_bounds__(256) glif_kernel(
    const float* __restrict__ x,
    const float* __restrict__ alpha,
    const float* __restrict__ beta,
    const float* __restrict__ gamma,
    const float* __restrict__ tau,
    const float* __restrict__ Vth,
    const float* __restrict__ leak,
    const float* __restrict__ reVth,
    const float* __restrict__ conduct,
    float* __restrict__ out)
{
    // Packed per-channel constants for this block's 16 channels.
    // Slots: 0=A 1=negGa 2=negLk 3=negR 4=vth 5..8=s0..s3
    __shared__ float2 spk[ROWS_PER_BLK][9];

    const int tid = threadIdx.x;
    const int r0  = blockIdx.x * ROWS_PER_BLK;            // first global row
    const int c0  = r0 & (GLIF_PLANE - 1);                // first channel (rows never cross b)

    const float4* xp = reinterpret_cast<const float4*>(x)   + (size_t)r0 * (GLIF_L / 4) + tid;
    float4*       op = reinterpret_cast<float4*>(out)       + (size_t)r0 * (GLIF_L / 4) + tid;

    // ---- prefetch chunk 0 (rows 0..3) — independent of params ----
    float4 xv[4];
#pragma unroll
    for (int u = 0; u < 4; ++u)
        xv[u] = __ldcs(xp + u * 256);

    // ---- params: 128 lanes, one sigmoid each (16 channels x 8 params) ----
    if (tid < 128) {
        const int ch   = tid >> 3;            // 0..15
        const int pidx = tid & 7;             // 0..7
        const int c    = c0 + ch;

        const float al = (__ldg(&alpha[c]) > 0.0f) ? 1.0f : 0.0f;  // arch_act(sigmoid)==(p>0)
        const float be = (__ldg(&beta[c])  > 0.0f) ? 1.0f : 0.0f;
        const float ga = (__ldg(&gamma[c]) > 0.0f) ? 1.0f : 0.0f;

        float v;
        if      (pidx == 0) v = __ldg(&tau[c]);
        else if (pidx == 1) v = __ldg(&Vth[c]);
        else if (pidx == 2) v = __ldg(&leak[c]);
        else if (pidx == 3) v = __ldg(&reVth[c]);
        else                v = __ldg(&conduct[(pidx - 4) * GLIF_PLANE + c]);

        const float sig = 1.0f / (1.0f + expf(-v));

        float r;
        int slot;
        if (pidx == 0) {
            r = 1.0f - al * (1.0f - sig);  slot = 0;        // A
            spk[ch][1] = make_float2(-ga, -ga);             // negGa
        } else if (pidx == 1) {
            r = sig;                       slot = 4;        // vth
        } else if (pidx == 2) {
            r = -((1.0f - al) * sig);      slot = 2;        // negLk
        } else if (pidx == 3) {
            r = -((1.0f - ga) * sig);      slot = 3;        // negR
        } else {
            r = 1.0f - be * (1.0f - sig);  slot = 5 + (pidx - 4);  // s_t
        }
        spk[ch][slot] = make_float2(r, r);
    }
    __syncthreads();

    const uint64_t one2 = pk2(1.0f, 1.0f);

    // ---- 16 rows, double-buffered in chunks of 4 ----
#pragma unroll
    for (int chunk = 0; chunk < 4; ++chunk) {
        float4 nv[4];
        if (chunk < 3) {
#pragma unroll
            for (int u = 0; u < 4; ++u)
                nv[u] = __ldcs(xp + ((chunk + 1) * 4 + u) * 256);
        }

#pragma unroll
        for (int u = 0; u < 4; ++u) {
            const int i = chunk * 4 + u;    // row / channel index within block
            const uint64_t* pc = reinterpret_cast<const uint64_t*>(&spk[i][0]);
            const uint64_t A2     = pc[0];
            const uint64_t negGa2 = pc[1];
            const uint64_t negLk2 = pc[2];
            const uint64_t negR2  = pc[3];
            const float    vth    = spk[i][4].x;
            const uint64_t s02    = pc[5];
            const uint64_t s12    = pc[6];
            const uint64_t s22    = pc[7];
            const uint64_t s32    = pc[8];
            const uint64_t sT2[3] = {s12, s22, s32};

            const float4 xq = xv[u];
            float oo[4];

#pragma unroll
            for (int p = 0; p < 2; ++p) {
                const uint64_t x2 = (p == 0) ? pk2(xq.x, xq.y) : pk2(xq.z, xq.w);

                // t=0: u=0, o=0 -> u1 = x*s0 - Lk
                uint64_t m = fma2_(x2, s02, negLk2);
                float mlo, mhi;
                upk2(m, mlo, mhi);
                float olo = setgt_(mlo, vth);
                float ohi = setgt_(mhi, vth);

#pragma unroll
                for (int t = 0; t < 3; ++t) {
                    const uint64_t o2 = pk2(olo, ohi);
                    // reference order: ((A*u)*(1-ga*o) - Lk) + x*s - R*o
                    const uint64_t g = fma2_(negGa2, o2, one2);  // exact: o,ga in {0,1}
                    uint64_t a = mul2_(A2, m);
                    a = mul2_(a, g);
                    a = add2_(a, negLk2);
                    a = fma2_(x2, sT2[t], a);
                    m = fma2_(negR2, o2, a);                     // exact: o in {0,1}
                    upk2(m, mlo, mhi);
                    olo = setgt_(mlo, vth);
                    ohi = setgt_(mhi, vth);
                }
                oo[2 * p]     = olo;
                oo[2 * p + 1] = ohi;
            }

            float4 res;
            res.x = oo[0]; res.y = oo[1]; res.z = oo[2]; res.w = oo[3];
            __stcs(op + i * 256, res);
        }

#pragma unroll
        for (int u = 0; u < 4; ++u) xv[u] = nv[u];
    }
}

extern "C" void kernel_launch(void* const* d_in, const int* in_sizes, int n_in,
                              void* d_out, int out_size) {
    const float* x       = (const float*)d_in[0];
    const float* alpha   = (const float*)d_in[1];
    const float* beta    = (const float*)d_in[2];
    const float* gamma   = (const float*)d_in[3];
    const float* tau     = (const float*)d_in[4];
    const float* Vth     = (const float*)d_in[5];
    const float* leak    = (const float*)d_in[6];
    const float* reVth   = (const float*)d_in[7];
    const float* conduct = (const float*)d_in[8];
    float* out = (float*)d_out;

    const int n_blk = out_size / (GLIF_L * ROWS_PER_BLK);   // 2048
    glif_kernel<<<n_blk, 256>>>(x, alpha, beta, gamma, tau, Vth,
                                leak, reVth, conduct, out);
}

// round 10
// speedup vs baseline: 1.1136x; 1.0261x over previous
#include <cuda_runtime.h>
#include <cuda_bf16.h>
#include <math.h>

// GLIF recurrence, T=4. Two kernels:
//  1) params: 2048 ch x 8 params = 16384 threads, ONE sigmoid each -> table.
//  2) main:   grid 16384, 256 thr; block = (channel, batch-pair); each thread
//     processes two float4 (same channel, batches bh and bh+8). regs ~34,
//     high occupancy + MLP 2.
//
// x: (B=16, PLANE=2048, L=1024) fp32. out: final spike map, fp32 {0,1}.

#define GLIF_T     4
#define GLIF_PLANE 2048
#define GLIF_L     1024
#define GLIF_B     16

// Per-channel constants, 48B (3 x float4):
// [0] A      [1] omg   [2] negLk [3] negR
// [4] vth    [5] s0    [6] s1    [7] s2
// [8] s3     [9..11] pad
struct __align__(16) ChParams {
    float v[12];
};
__device__ ChParams g_chp[GLIF_PLANE];

__global__ void glif_params_kernel(
    const float* __restrict__ alpha,
    const float* __restrict__ beta,
    const float* __restrict__ gamma,
    const float* __restrict__ tau,
    const float* __restrict__ Vth,
    const float* __restrict__ leak,
    const float* __restrict__ reVth,
    const float* __restrict__ conduct)
{
    const int idx = blockIdx.x * blockDim.x + threadIdx.x;
    if (idx >= GLIF_PLANE * 8) return;
    const int c    = idx >> 3;
    const int pidx = idx & 7;

    const float al = (__ldg(&alpha[c]) > 0.0f) ? 1.0f : 0.0f;  // arch_act(sigmoid)==(p>0)
    const float be = (__ldg(&beta[c])  > 0.0f) ? 1.0f : 0.0f;
    const float ga = (__ldg(&gamma[c]) > 0.0f) ? 1.0f : 0.0f;

    float v;
    if      (pidx == 0) v = __ldg(&tau[c]);
    else if (pidx == 1) v = __ldg(&Vth[c]);
    else if (pidx == 2) v = __ldg(&leak[c]);
    else if (pidx == 3) v = __ldg(&reVth[c]);
    else                v = __ldg(&conduct[(pidx - 4) * GLIF_PLANE + c]);

    const float sig = 1.0f / (1.0f + expf(-v));

    float r;
    int slot;
    if (pidx == 0) {
        r = 1.0f - al * (1.0f - sig);  slot = 0;            // A
        g_chp[c].v[1] = 1.0f - ga;                          // omg
        g_chp[c].v[9] = 0.0f; g_chp[c].v[10] = 0.0f; g_chp[c].v[11] = 0.0f;
    } else if (pidx == 1) {
        r = sig;                       slot = 4;            // vth
    } else if (pidx == 2) {
        r = -((1.0f - al) * sig);      slot = 2;            // negLk
    } else if (pidx == 3) {
        r = -((1.0f - ga) * sig);      slot = 3;            // negR
    } else {
        r = 1.0f - be * (1.0f - sig);  slot = 5 + (pidx - 4);  // s_t
    }
    g_chp[c].v[slot] = r;
}

__global__ void __launch_bounds__(256) glif_main_kernel(
    const float* __restrict__ x,
    float* __restrict__ out)
{
    const int c  = blockIdx.x & (GLIF_PLANE - 1);   // channel
    const int bh = blockIdx.x >> 11;                // 0..7 -> batches bh, bh+8

    // Per-channel constants: 3 broadcast float4 loads (L1 hit after first use)
    const float4* pv = reinterpret_cast<const float4*>(&g_chp[c]);
    const float4 p0 = __ldg(pv);
    const float4 p1 = __ldg(pv + 1);
    const float  s3 = __ldg(&g_chp[c].v[8]);
    const float A = p0.x, omg = p0.y, negLk = p0.z, negR = p0.w;
    const float vth = p1.x, s0 = p1.y;
    const float sv[3] = {p1.z, p1.w, s3};

    const size_t row4  = (size_t)GLIF_PLANE * (GLIF_L / 4);     // float4 per batch
    const size_t base4 = (size_t)bh * row4 + (size_t)c * (GLIF_L / 4) + threadIdx.x;
    const float4* xp = reinterpret_cast<const float4*>(x) + base4;
    float4*       op = reinterpret_cast<float4*>(out) + base4;

    // Two independent float4 streams (8 MiB apart) -> MLP 2
    const float4 xa = __ldcs(xp);
    const float4 xb = __ldcs(xp + 8 * row4);

#pragma unroll
    for (int q = 0; q < 2; ++q) {
        const float4 xq = (q == 0) ? xa : xb;
        float xl[4] = {xq.x, xq.y, xq.z, xq.w};
        float ov[4];
#pragma unroll
        for (int j = 0; j < 4; ++j) {
            const float xj = xl[j];
            // t=0: u=0, o=0 -> u1 = x*s0 - Lk
            float uu = fmaf(xj, s0, negLk);
            bool  o  = (uu > vth);
#pragma unroll
            for (int t = 0; t < 3; ++t) {
                // reference order: ((A*u)*(1-ga*o) - Lk) + x*s - R*o
                const float g = o ? omg : 1.0f;
                float m = (A * uu) * g;
                m = m + negLk;
                m = fmaf(xj, sv[t], m);
                if (o) m = m + negR;
                o = (m > vth);
                uu = m;
            }
            ov[j] = o ? 1.0f : 0.0f;
        }
        float4 res;
        res.x = ov[0]; res.y = ov[1]; res.z = ov[2]; res.w = ov[3];
        __stcs(op + (size_t)(q * 8) * row4, res);
    }
}

extern "C" void kernel_launch(void* const* d_in, const int* in_sizes, int n_in,
                              void* d_out, int out_size) {
    const float* x       = (const float*)d_in[0];
    const float* alpha   = (const float*)d_in[1];
    const float* beta    = (const float*)d_in[2];
    const float* gamma   = (const float*)d_in[3];
    const float* tau     = (const float*)d_in[4];
    const float* Vth     = (const float*)d_in[5];
    const float* leak    = (const float*)d_in[6];
    const float* reVth   = (const float*)d_in[7];
    const float* conduct = (const float*)d_in[8];
    float* out = (float*)d_out;

    glif_params_kernel<<<(GLIF_PLANE * 8 + 255) / 256, 256>>>(
        alpha, beta, gamma, tau, Vth, leak, reVth, conduct);

    const int n_blk = out_size / (GLIF_L * 2);   // 16384 blocks, 2 batches each
    glif_main_kernel<<<n_blk, 256>>>(x, out);
}

// round 11
// speedup vs baseline: 1.1233x; 1.0088x over previous
#include <cuda_runtime.h>
#include <cuda_bf16.h>
#include <math.h>

// GLIF recurrence, T=4. Two kernels:
//  1) params: 2048 ch x 8 params = 16384 threads, ONE sigmoid each -> table.
//  2) main:   grid 16384, 256 thr; block = (channel, batch-pair); each thread
//     processes two float4 (same channel, batches bh and bh+8). regs ~34,
//     high occupancy + MLP 2.
//
// x: (B=16, PLANE=2048, L=1024) fp32. out: final spike map, fp32 {0,1}.

#define GLIF_T     4
#define GLIF_PLANE 2048
#define GLIF_L     1024
#define GLIF_B     16

// Per-channel constants, 48B (3 x float4):
// [0] A      [1] omg   [2] negLk [3] negR
// [4] vth    [5] s0    [6] s1    [7] s2
// [8] s3     [9..11] pad
struct __align__(16) ChParams {
    float v[12];
};
__device__ ChParams g_chp[GLIF_PLANE];

__global__ void glif_params_kernel(
    const float* __restrict__ alpha,
    const float* __restrict__ beta,
    const float* __restrict__ gamma,
    const float* __restrict__ tau,
    const float* __restrict__ Vth,
    const float* __restrict__ leak,
    const float* __restrict__ reVth,
    const float* __restrict__ conduct)
{
    const int idx = blockIdx.x * blockDim.x + threadIdx.x;
    if (idx >= GLIF_PLANE * 8) return;
    const int c    = idx >> 3;
    const int pidx = idx & 7;

    const float al = (__ldg(&alpha[c]) > 0.0f) ? 1.0f : 0.0f;  // arch_act(sigmoid)==(p>0)
    const float be = (__ldg(&beta[c])  > 0.0f) ? 1.0f : 0.0f;
    const float ga = (__ldg(&gamma[c]) > 0.0f) ? 1.0f : 0.0f;

    float v;
    if      (pidx == 0) v = __ldg(&tau[c]);
    else if (pidx == 1) v = __ldg(&Vth[c]);
    else if (pidx == 2) v = __ldg(&leak[c]);
    else if (pidx == 3) v = __ldg(&reVth[c]);
    else                v = __ldg(&conduct[(pidx - 4) * GLIF_PLANE + c]);

    const float sig = 1.0f / (1.0f + expf(-v));

    float r;
    int slot;
    if (pidx == 0) {
        r = 1.0f - al * (1.0f - sig);  slot = 0;            // A
        g_chp[c].v[1] = 1.0f - ga;                          // omg
        g_chp[c].v[9] = 0.0f; g_chp[c].v[10] = 0.0f; g_chp[c].v[11] = 0.0f;
    } else if (pidx == 1) {
        r = sig;                       slot = 4;            // vth
    } else if (pidx == 2) {
        r = -((1.0f - al) * sig);      slot = 2;            // negLk
    } else if (pidx == 3) {
        r = -((1.0f - ga) * sig);      slot = 3;            // negR
    } else {
        r = 1.0f - be * (1.0f - sig);  slot = 5 + (pidx - 4);  // s_t
    }
    g_chp[c].v[slot] = r;
}

__global__ void __launch_bounds__(256) glif_main_kernel(
    const float* __restrict__ x,
    float* __restrict__ out)
{
    const int c  = blockIdx.x & (GLIF_PLANE - 1);   // channel
    const int bh = blockIdx.x >> 11;                // 0..7 -> batches bh, bh+8

    // Per-channel constants: 3 broadcast float4 loads (L1 hit after first use)
    const float4* pv = reinterpret_cast<const float4*>(&g_chp[c]);
    const float4 p0 = __ldg(pv);
    const float4 p1 = __ldg(pv + 1);
    const float  s3 = __ldg(&g_chp[c].v[8]);
    const float A = p0.x, omg = p0.y, negLk = p0.z, negR = p0.w;
    const float vth = p1.x, s0 = p1.y;
    const float sv[3] = {p1.z, p1.w, s3};

    const size_t row4  = (size_t)GLIF_PLANE * (GLIF_L / 4);     // float4 per batch
    const size_t base4 = (size_t)bh * row4 + (size_t)c * (GLIF_L / 4) + threadIdx.x;
    const float4* xp = reinterpret_cast<const float4*>(x) + base4;
    float4*       op = reinterpret_cast<float4*>(out) + base4;

    // Two independent float4 streams (8 MiB apart) -> MLP 2
    const float4 xa = __ldcs(xp);
    const float4 xb = __ldcs(xp + 8 * row4);

#pragma unroll
    for (int q = 0; q < 2; ++q) {
        const float4 xq = (q == 0) ? xa : xb;
        float xl[4] = {xq.x, xq.y, xq.z, xq.w};
        float ov[4];
#pragma unroll
        for (int j = 0; j < 4; ++j) {
            const float xj = xl[j];
            // t=0: u=0, o=0 -> u1 = x*s0 - Lk
            float uu = fmaf(xj, s0, negLk);
            bool  o  = (uu > vth);
#pragma unroll
            for (int t = 0; t < 3; ++t) {
                // reference order: ((A*u)*(1-ga*o) - Lk) + x*s - R*o
                const float g = o ? omg : 1.0f;
                float m = (A * uu) * g;
                m = m + negLk;
                m = fmaf(xj, sv[t], m);
                if (o) m = m + negR;
                o = (m > vth);
                uu = m;
            }
            ov[j] = o ? 1.0f : 0.0f;
        }
        float4 res;
        res.x = ov[0]; res.y = ov[1]; res.z = ov[2]; res.w = ov[3];
        __stcs(op + (size_t)(q * 8) * row4, res);
    }
}

extern "C" void kernel_launch(void* const* d_in, const int* in_sizes, int n_in,
                              void* d_out, int out_size) {
    const float* x       = (const float*)d_in[0];
    const float* alpha   = (const float*)d_in[1];
    const float* beta    = (const float*)d_in[2];
    const float* gamma   = (const float*)d_in[3];
    const float* tau     = (const float*)d_in[4];
    const float* Vth     = (const float*)d_in[5];
    const float* leak    = (const float*)d_in[6];
    const float* reVth   = (const float*)d_in[7];
    const float* conduct = (const float*)d_in[8];
    float* out = (float*)d_out;

    glif_params_kernel<<<(GLIF_PLANE * 8 + 255) / 256, 256>>>(
        alpha, beta, gamma, tau, Vth, leak, reVth, conduct);

    const int n_blk = out_size / (GLIF_L * 2);   // 16384 blocks, 2 batches each
    glif_main_kernel<<<n_blk, 256>>>(x, out);
}